// round 3
// baseline (speedup 1.0000x reference)
#include <cuda_runtime.h>
#include <math.h>

#define SEQ 1024
#define DM 768
#define DI 1536
#define DTR 48
#define DST 16
#define NLAYER 4
#define NVOCAB 32000
#define PROJW 80   // DTR + 2*DST

// ---------------- scratch (device globals; no allocation allowed) ----------------
__device__ float g_x[SEQ * DM];        // residual stream
__device__ float g_h[SEQ * DM];        // rmsnorm output
__device__ float g_xz[SEQ * 2 * DI];   // in_proj output (xi | res)
__device__ float g_xc[SEQ * DI];       // conv+silu output (u); overwritten with y by scan
__device__ float g_proj[SEQ * PROJW];  // x_proj output
__device__ float g_dt[SEQ * DI];       // softplus(dt)
__device__ float g_gated[SEQ * DI];    // y * silu(res)

// ---------------- embedding gather ----------------
__global__ void gather_kernel(const int* __restrict__ tokens,
                              const float* __restrict__ emb,
                              float* __restrict__ x) {
    int t = blockIdx.x;
    int tok = tokens[t];
    const float* src = emb + (size_t)tok * DM;
    for (int c = threadIdx.x; c < DM; c += blockDim.x)
        x[t * DM + c] = src[c];
}

// ---------------- rmsnorm ----------------
__global__ void rmsnorm_kernel(const float* __restrict__ in,
                               const float* __restrict__ w,
                               float* __restrict__ out) {
    int t = blockIdx.x;
    const float* row = in + t * DM;
    __shared__ float red[8];
    float s = 0.f;
    for (int c = threadIdx.x; c < DM; c += 256) {
        float v = row[c];
        s += v * v;
    }
    // intra-warp reduce (all 32 lanes active, full mask: safe)
    #pragma unroll
    for (int o = 16; o; o >>= 1) s += __shfl_xor_sync(0xffffffffu, s, o);
    if ((threadIdx.x & 31) == 0) red[threadIdx.x >> 5] = s;
    __syncthreads();
    // cross-warp combine WITHOUT divergent shuffles: every thread sums the 8
    // partials from shared memory (broadcast loads, conflict-free).
    float tot = 0.f;
    #pragma unroll
    for (int i = 0; i < 8; i++) tot += red[i];
    float rs = rsqrtf(tot * (1.0f / DM) + 1e-5f);
    for (int c = threadIdx.x; c < DM; c += 256)
        out[t * DM + c] = row[c] * rs * w[c];
}

// ---------------- generic NT gemm: C[M,N] = A[M,K] * B[N,K]^T (+ beta*C + bias, act) ----------------
// 128x128 block tile, 8x8 per thread, BK=8, 256 threads.
#define BM 128
#define BN 128
#define BK 8
#define TM 8
#define TN 8

__global__ __launch_bounds__(256) void gemm_nt_kernel(
    const float* __restrict__ A, int lda,
    const float* __restrict__ B, int ldb,
    float* __restrict__ C, int ldc,
    int M, int N, int K,
    const float* __restrict__ bias, int act, float beta)
{
    __shared__ float As[BK][BM];
    __shared__ float Bs[BK][BN];

    int bm = blockIdx.y * BM;
    int bn = blockIdx.x * BN;
    int tid = threadIdx.x;
    int tx = tid & 15;       // 0..15 -> N direction
    int ty = tid >> 4;       // 0..15 -> M direction

    int lrow = tid >> 1;         // 0..127
    int lcol = (tid & 1) * 4;    // 0 or 4

    float acc[TM][TN];
    #pragma unroll
    for (int i = 0; i < TM; i++)
        #pragma unroll
        for (int j = 0; j < TN; j++) acc[i][j] = 0.f;

    for (int k0 = 0; k0 < K; k0 += BK) {
        // load A tile
        {
            float4 v = make_float4(0.f, 0.f, 0.f, 0.f);
            int r = bm + lrow;
            if (r < M) {
                if (k0 + lcol + 3 < K) {
                    v = *(const float4*)(A + (size_t)r * lda + k0 + lcol);
                } else {
                    float tmp[4];
                    #pragma unroll
                    for (int i = 0; i < 4; i++)
                        tmp[i] = (k0 + lcol + i < K) ? A[(size_t)r * lda + k0 + lcol + i] : 0.f;
                    v = make_float4(tmp[0], tmp[1], tmp[2], tmp[3]);
                }
            }
            As[lcol + 0][lrow] = v.x;
            As[lcol + 1][lrow] = v.y;
            As[lcol + 2][lrow] = v.z;
            As[lcol + 3][lrow] = v.w;
        }
        // load B tile
        {
            float4 v = make_float4(0.f, 0.f, 0.f, 0.f);
            int r = bn + lrow;
            if (r < N) {
                if (k0 + lcol + 3 < K) {
                    v = *(const float4*)(B + (size_t)r * ldb + k0 + lcol);
                } else {
                    float tmp[4];
                    #pragma unroll
                    for (int i = 0; i < 4; i++)
                        tmp[i] = (k0 + lcol + i < K) ? B[(size_t)r * ldb + k0 + lcol + i] : 0.f;
                    v = make_float4(tmp[0], tmp[1], tmp[2], tmp[3]);
                }
            }
            Bs[lcol + 0][lrow] = v.x;
            Bs[lcol + 1][lrow] = v.y;
            Bs[lcol + 2][lrow] = v.z;
            Bs[lcol + 3][lrow] = v.w;
        }
        __syncthreads();

        #pragma unroll
        for (int k = 0; k < BK; k++) {
            float a[TM], b[TN];
            #pragma unroll
            for (int i = 0; i < TM; i++) a[i] = As[k][ty * TM + i];
            #pragma unroll
            for (int j = 0; j < TN; j++) b[j] = Bs[k][tx * TN + j];
            #pragma unroll
            for (int i = 0; i < TM; i++)
                #pragma unroll
                for (int j = 0; j < TN; j++)
                    acc[i][j] = fmaf(a[i], b[j], acc[i][j]);
        }
        __syncthreads();
    }

    #pragma unroll
    for (int i = 0; i < TM; i++) {
        int r = bm + ty * TM + i;
        if (r >= M) continue;
        #pragma unroll
        for (int j = 0; j < TN; j++) {
            int c = bn + tx * TN + j;
            if (c >= N) continue;
            float v = acc[i][j];
            if (beta != 0.f) v += beta * C[(size_t)r * ldc + c];
            if (bias) v += bias[c];
            if (act == 1) {
                // softplus
                v = (v > 20.f) ? v : log1pf(expf(v));
            }
            C[(size_t)r * ldc + c] = v;
        }
    }
}

// ---------------- causal depthwise conv (width 4) + silu ----------------
__global__ void conv_silu_kernel(const float* __restrict__ xz,
                                 const float* __restrict__ w,
                                 const float* __restrict__ b,
                                 float* __restrict__ out) {
    int c = blockIdx.x * 256 + threadIdx.x;
    int t = blockIdx.y;
    if (c >= DI) return;
    float acc = b[c];
    #pragma unroll
    for (int j = 0; j < 4; j++) {
        int tt = t - 3 + j;
        if (tt >= 0) acc = fmaf(xz[tt * (2 * DI) + c], w[c * 4 + j], acc);
    }
    float sg = 1.f / (1.f + __expf(-acc));
    out[t * DI + c] = acc * sg;
}

// ---------------- selective scan ----------------
// Reference: A_cum_l = exp(cumsum of exp(dt_j*A)); h = bdu/(A_cum+1e-12);
//            y_l = cumsum(h)*A_cum_l dot C.  Equivalent stable recurrence:
//            z <- exp(exp(dt_l*A)) * z + dt_l*u_l*B_l[n];  y_l = sum_n z*C_l[n] + u*D.
// One (d,n) pair per lane; 16 lanes (one half-warp) per channel d.
// NOTE: ea enters a ~1024-term cumulative product -> use precise expf there;
//       a's error is additive-in-exponent and tiny -> fast __expf is fine.
__global__ void scan_kernel(float* __restrict__ u_y,          // in u, out y  (SEQ x DI)
                            const float* __restrict__ dt,     // SEQ x DI
                            const float* __restrict__ proj,   // SEQ x 80
                            const float* __restrict__ A_log,  // DI x 16
                            const float* __restrict__ Dsk)    // DI
{
    int d = blockIdx.x * 16 + (threadIdx.x >> 4);
    int n = threadIdx.x & 15;
    float An = -__expf(A_log[d * DST + n]);
    float Dv = Dsk[d];
    float z = 0.f;
    for (int t = 0; t < SEQ; t++) {
        float dtv = dt[t * DI + d];
        float u   = u_y[t * DI + d];
        float a   = __expf(dtv * An);   // in (0,1]
        float ea  = expf(a);            // precise: compounds over 1024 steps
        float bdu = dtv * u * proj[t * PROJW + DTR + n];
        z = fmaf(ea, z, bdu);
        float c = z * proj[t * PROJW + DTR + DST + n];
        c += __shfl_xor_sync(0xffffffffu, c, 8, 16);
        c += __shfl_xor_sync(0xffffffffu, c, 4, 16);
        c += __shfl_xor_sync(0xffffffffu, c, 2, 16);
        c += __shfl_xor_sync(0xffffffffu, c, 1, 16);
        if (n == 0) u_y[t * DI + d] = c + u * Dv;
    }
}

// ---------------- gate: gated = y * silu(res) ----------------
__global__ void gate_kernel(const float* __restrict__ y,
                            const float* __restrict__ xz,
                            float* __restrict__ out) {
    int idx = blockIdx.x * 256 + threadIdx.x;
    if (idx >= SEQ * DI) return;
    int t = idx / DI;
    int d = idx - t * DI;
    float r = xz[t * 2 * DI + DI + d];
    float sg = r / (1.f + __expf(-r));
    out[idx] = y[idx] * sg;
}

// ---------------- host launcher ----------------
extern "C" void kernel_launch(void* const* d_in, const int* in_sizes, int n_in,
                              void* d_out, int out_size) {
    const int*   tokens       = (const int*)d_in[0];
    const float* embedding    = (const float*)d_in[1];
    const float* norm_w       = (const float*)d_in[2];
    const float* in_proj_w    = (const float*)d_in[3];
    const float* conv_w       = (const float*)d_in[4];
    const float* conv_b       = (const float*)d_in[5];
    const float* x_proj_w     = (const float*)d_in[6];
    const float* dt_proj_w    = (const float*)d_in[7];
    const float* dt_proj_b    = (const float*)d_in[8];
    const float* A_log        = (const float*)d_in[9];
    const float* D_skip       = (const float*)d_in[10];
    const float* out_proj_w   = (const float*)d_in[11];
    const float* final_norm_w = (const float*)d_in[12];
    float* out = (float*)d_out;

    float *px, *ph, *pxz, *pxc, *pproj, *pdt, *pgated;
    cudaGetSymbolAddress((void**)&px,     g_x);
    cudaGetSymbolAddress((void**)&ph,     g_h);
    cudaGetSymbolAddress((void**)&pxz,    g_xz);
    cudaGetSymbolAddress((void**)&pxc,    g_xc);
    cudaGetSymbolAddress((void**)&pproj,  g_proj);
    cudaGetSymbolAddress((void**)&pdt,    g_dt);
    cudaGetSymbolAddress((void**)&pgated, g_gated);

    gather_kernel<<<SEQ, 256>>>(tokens, embedding, px);

    for (int i = 0; i < NLAYER; i++) {
        // h = rmsnorm(x, norm_w[i])
        rmsnorm_kernel<<<SEQ, 256>>>(px, norm_w + i * DM, ph);

        // xz = h @ in_proj_w[i].T   (1024 x 3072)
        gemm_nt_kernel<<<dim3((2 * DI + BN - 1) / BN, SEQ / BM), 256>>>(
            ph, DM, in_proj_w + (size_t)i * 2 * DI * DM, DM,
            pxz, 2 * DI, SEQ, 2 * DI, DM, nullptr, 0, 0.f);

        // xi = silu(conv(xz[:, :DI]))
        conv_silu_kernel<<<dim3(DI / 256, SEQ), 256>>>(
            pxz, conv_w + (size_t)i * DI * 4, conv_b + i * DI, pxc);

        // proj = xi @ x_proj_w[i].T   (1024 x 80)
        gemm_nt_kernel<<<dim3((PROJW + BN - 1) / BN, SEQ / BM), 256>>>(
            pxc, DI, x_proj_w + (size_t)i * PROJW * DI, DI,
            pproj, PROJW, SEQ, PROJW, DI, nullptr, 0, 0.f);

        // dt = softplus(proj[:, :48] @ dt_proj_w[i].T + dt_proj_b[i])   (1024 x 1536)
        gemm_nt_kernel<<<dim3((DI + BN - 1) / BN, SEQ / BM), 256>>>(
            pproj, PROJW, dt_proj_w + (size_t)i * DI * DTR, DTR,
            pdt, DI, SEQ, DI, DTR, dt_proj_b + i * DI, 1, 0.f);

        // selective scan: pxc (u) -> pxc (y)
        scan_kernel<<<DI / 16, 256>>>(
            pxc, pdt, pproj, A_log + (size_t)i * DI * DST, D_skip + i * DI);

        // gated = y * silu(res)
        gate_kernel<<<(SEQ * DI + 255) / 256, 256>>>(pxc, pxz, pgated);

        // x = x + gated @ out_proj_w[i].T   (1024 x 768)
        gemm_nt_kernel<<<dim3((DM + BN - 1) / BN, SEQ / BM), 256>>>(
            pgated, DI, out_proj_w + (size_t)i * DM * DI, DI,
            px, DM, SEQ, DM, DI, nullptr, 0, 1.f);
    }

    // final rmsnorm + logits
    rmsnorm_kernel<<<SEQ, 256>>>(px, final_norm_w, ph);
    gemm_nt_kernel<<<dim3((NVOCAB + BN - 1) / BN, SEQ / BM), 256>>>(
        ph, DM, embedding, DM,
        out, NVOCAB, SEQ, NVOCAB, DM, nullptr, 0, 0.f);
}

// round 6
// speedup vs baseline: 1.9568x; 1.9568x over previous
#include <cuda_runtime.h>
#include <cuda_bf16.h>
#include <math.h>

#define SEQ 1024
#define DM 768
#define DI 1536
#define DTR 48
#define DST 16
#define NLAYER 4
#define NVOCAB 32000
#define PROJW 80   // DTR + 2*DST

#define K3_DM (3 * DM)    // 2304
#define K3_DI (3 * DI)    // 4608

// ---------------- scratch (device globals; no allocation allowed) ----------------
__device__ float g_x[SEQ * DM];        // residual stream
__device__ float g_h[SEQ * DM];        // rmsnorm output
__device__ float g_xz[SEQ * 2 * DI];   // in_proj output (xi | res)
__device__ float g_xc[SEQ * DI];       // conv+silu output (u); overwritten with y by scan
__device__ float g_proj[SEQ * PROJW];  // x_proj output
__device__ float g_dt[SEQ * DI];       // softplus(dt)
__device__ float g_gated[SEQ * DI];    // y * silu(res)

// split-3 bf16 weight / activation scratch
__device__ __nv_bfloat16 g_w_logits[(size_t)NVOCAB * K3_DM];          // 147 MB
__device__ __nv_bfloat16 g_w_in[(size_t)NLAYER * 2 * DI * K3_DM];     // 56 MB
__device__ __nv_bfloat16 g_w_out[(size_t)NLAYER * DM * K3_DI];        // 28 MB
__device__ __nv_bfloat16 g_a3[(size_t)SEQ * K3_DI];                   // 9.4 MB (max K'=4608)

// ---------------- fp32 -> (hi,lo) bf16 split ----------------
__device__ __forceinline__ void split_bf16(float v, __nv_bfloat16& hi, __nv_bfloat16& lo) {
    hi = __float2bfloat16_rn(v);
    lo = __float2bfloat16_rn(v - __bfloat162float(hi));
}

// weights: out[n][0:K]=hi, [K:2K]=hi, [2K:3K]=lo
__global__ void split3_B_kernel(const float* __restrict__ W,
                                __nv_bfloat16* __restrict__ out,
                                int N, int K) {
    size_t idx = (size_t)blockIdx.x * 256 + threadIdx.x;
    if (idx >= (size_t)N * K) return;
    int n = (int)(idx / K);
    int k = (int)(idx - (size_t)n * K);
    __nv_bfloat16 hi, lo;
    split_bf16(W[idx], hi, lo);
    __nv_bfloat16* row = out + (size_t)n * 3 * K;
    row[k] = hi;
    row[K + k] = hi;
    row[2 * K + k] = lo;
}

// activations: out[m][0:K]=hi, [K:2K]=lo, [2K:3K]=hi
__global__ void split3_A_kernel(const float* __restrict__ Xm,
                                __nv_bfloat16* __restrict__ out,
                                int M, int K) {
    size_t idx = (size_t)blockIdx.x * 256 + threadIdx.x;
    if (idx >= (size_t)M * K) return;
    int m = (int)(idx / K);
    int k = (int)(idx - (size_t)m * K);
    __nv_bfloat16 hi, lo;
    split_bf16(Xm[idx], hi, lo);
    __nv_bfloat16* row = out + (size_t)m * 3 * K;
    row[k] = hi;
    row[K + k] = lo;
    row[2 * K + k] = hi;
}

// ---------------- embedding gather ----------------
__global__ void gather_kernel(const int* __restrict__ tokens,
                              const float* __restrict__ emb,
                              float* __restrict__ x) {
    int t = blockIdx.x;
    int tok = tokens[t];
    const float* src = emb + (size_t)tok * DM;
    for (int c = threadIdx.x; c < DM; c += blockDim.x)
        x[t * DM + c] = src[c];
}

// ---------------- rmsnorm ----------------
__global__ void rmsnorm_kernel(const float* __restrict__ in,
                               const float* __restrict__ w,
                               float* __restrict__ out) {
    int t = blockIdx.x;
    const float* row = in + t * DM;
    __shared__ float red[8];
    float s = 0.f;
    for (int c = threadIdx.x; c < DM; c += 256) {
        float v = row[c];
        s += v * v;
    }
    #pragma unroll
    for (int o = 16; o; o >>= 1) s += __shfl_xor_sync(0xffffffffu, s, o);
    if ((threadIdx.x & 31) == 0) red[threadIdx.x >> 5] = s;
    __syncthreads();
    float tot = 0.f;
    #pragma unroll
    for (int i = 0; i < 8; i++) tot += red[i];
    float rs = rsqrtf(tot * (1.0f / DM) + 1e-5f);
    for (int c = threadIdx.x; c < DM; c += 256)
        out[t * DM + c] = row[c] * rs * w[c];
}

// ================= tensor-core bf16 NT GEMM =================
// C[M,N] = A[M,K']*B[N,K']^T, fp32 accumulate. M,N multiples of 128, K' of 32.
// Block 128x128, 8 warps (4 in M x 2 in N), warp tile 32x64, mma.m16n8k16.
#define SPAD 40  // smem row stride in bf16 elements (conflict-free, 16B-aligned)

__device__ __forceinline__ void mma_bf16(float* c, const unsigned* a, const unsigned* b) {
    asm volatile(
        "mma.sync.aligned.m16n8k16.row.col.f32.bf16.bf16.f32 "
        "{%0,%1,%2,%3}, {%4,%5,%6,%7}, {%8,%9}, {%0,%1,%2,%3};\n"
        : "+f"(c[0]), "+f"(c[1]), "+f"(c[2]), "+f"(c[3])
        : "r"(a[0]), "r"(a[1]), "r"(a[2]), "r"(a[3]), "r"(b[0]), "r"(b[1]));
}

__global__ __launch_bounds__(256) void gemm_bf16_nt_kernel(
    const __nv_bfloat16* __restrict__ A,
    const __nv_bfloat16* __restrict__ B,
    float* __restrict__ C, int ldc,
    int N, int K, int addC)
{
    __shared__ __nv_bfloat16 As[128 * SPAD];
    __shared__ __nv_bfloat16 Bs[128 * SPAD];

    const int tid  = threadIdx.x;
    const int lane = tid & 31;
    const int warp = tid >> 5;
    const int g = lane >> 2;      // group id (0..7)
    const int t = lane & 3;       // thread in group (0..3)
    const int wm = (warp >> 1) * 32;
    const int wn = (warp & 1) * 64;
    const int bm = blockIdx.y * 128;
    const int bn = blockIdx.x * 128;

    const __nv_bfloat16* Abase = A + (size_t)bm * K;
    const __nv_bfloat16* Bbase = B + (size_t)bn * K;

    // per-thread gmem tile loads: 2x float4 for A, 2x for B
    const int r0 = tid >> 2;            // 0..63
    const int c0 = (tid & 3) * 8;       // 0,8,16,24 (bf16 elems)

    float acc[2][8][4];
    #pragma unroll
    for (int f = 0; f < 2; f++)
        #pragma unroll
        for (int nf = 0; nf < 8; nf++)
            #pragma unroll
            for (int i = 0; i < 4; i++) acc[f][nf][i] = 0.f;

    const int niter = K / 32;

    // prologue: tile 0 -> smem
    {
        uint4 a0 = *(const uint4*)(Abase + (size_t)r0 * K + c0);
        uint4 a1 = *(const uint4*)(Abase + (size_t)(r0 + 64) * K + c0);
        uint4 b0 = *(const uint4*)(Bbase + (size_t)r0 * K + c0);
        uint4 b1 = *(const uint4*)(Bbase + (size_t)(r0 + 64) * K + c0);
        *(uint4*)&As[r0 * SPAD + c0] = a0;
        *(uint4*)&As[(r0 + 64) * SPAD + c0] = a1;
        *(uint4*)&Bs[r0 * SPAD + c0] = b0;
        *(uint4*)&Bs[(r0 + 64) * SPAD + c0] = b1;
    }
    __syncthreads();

    for (int kt = 0; kt < niter; kt++) {
        uint4 na0, na1, nb0, nb1;
        const bool has = (kt + 1 < niter);
        if (has) {
            int kn = (kt + 1) * 32;
            na0 = *(const uint4*)(Abase + (size_t)r0 * K + kn + c0);
            na1 = *(const uint4*)(Abase + (size_t)(r0 + 64) * K + kn + c0);
            nb0 = *(const uint4*)(Bbase + (size_t)r0 * K + kn + c0);
            nb1 = *(const uint4*)(Bbase + (size_t)(r0 + 64) * K + kn + c0);
        }

        #pragma unroll
        for (int ks = 0; ks < 2; ks++) {
            const int kk = ks * 16 + t * 2;
            unsigned a[2][4];
            #pragma unroll
            for (int f = 0; f < 2; f++) {
                int row = wm + f * 16;
                a[f][0] = *(const unsigned*)&As[(row + g) * SPAD + kk];
                a[f][1] = *(const unsigned*)&As[(row + g + 8) * SPAD + kk];
                a[f][2] = *(const unsigned*)&As[(row + g) * SPAD + kk + 8];
                a[f][3] = *(const unsigned*)&As[(row + g + 8) * SPAD + kk + 8];
            }
            unsigned b[8][2];
            #pragma unroll
            for (int nf = 0; nf < 8; nf++) {
                int col = wn + nf * 8 + g;
                b[nf][0] = *(const unsigned*)&Bs[col * SPAD + kk];
                b[nf][1] = *(const unsigned*)&Bs[col * SPAD + kk + 8];
            }
            #pragma unroll
            for (int f = 0; f < 2; f++)
                #pragma unroll
                for (int nf = 0; nf < 8; nf++)
                    mma_bf16(acc[f][nf], a[f], b[nf]);
        }
        __syncthreads();
        if (has) {
            *(uint4*)&As[r0 * SPAD + c0] = na0;
            *(uint4*)&As[(r0 + 64) * SPAD + c0] = na1;
            *(uint4*)&Bs[r0 * SPAD + c0] = nb0;
            *(uint4*)&Bs[(r0 + 64) * SPAD + c0] = nb1;
            __syncthreads();
        }
    }

    // epilogue
    #pragma unroll
    for (int f = 0; f < 2; f++) {
        int row = bm + wm + f * 16 + g;
        #pragma unroll
        for (int nf = 0; nf < 8; nf++) {
            int col = bn + wn + nf * 8 + t * 2;
            float* p0 = C + (size_t)row * ldc + col;
            float* p1 = C + (size_t)(row + 8) * ldc + col;
            if (addC) {
                p0[0] += acc[f][nf][0];
                p0[1] += acc[f][nf][1];
                p1[0] += acc[f][nf][2];
                p1[1] += acc[f][nf][3];
            } else {
                p0[0] = acc[f][nf][0];
                p0[1] = acc[f][nf][1];
                p1[0] = acc[f][nf][2];
                p1[1] = acc[f][nf][3];
            }
        }
    }
}

// ---------------- SIMT fp32 NT gemm (kept for dt_proj) ----------------
#define BM 128
#define BN 128
#define BK 8
#define TM 8
#define TN 8

__global__ __launch_bounds__(256) void gemm_nt_kernel(
    const float* __restrict__ A, int lda,
    const float* __restrict__ B, int ldb,
    float* __restrict__ C, int ldc,
    int M, int N, int K,
    const float* __restrict__ bias, int act, float beta)
{
    __shared__ float As[BK][BM];
    __shared__ float Bs[BK][BN];

    int bm = blockIdx.y * BM;
    int bn = blockIdx.x * BN;
    int tid = threadIdx.x;
    int tx = tid & 15;
    int ty = tid >> 4;

    int lrow = tid >> 1;
    int lcol = (tid & 1) * 4;

    float acc[TM][TN];
    #pragma unroll
    for (int i = 0; i < TM; i++)
        #pragma unroll
        for (int j = 0; j < TN; j++) acc[i][j] = 0.f;

    for (int k0 = 0; k0 < K; k0 += BK) {
        {
            float4 v = make_float4(0.f, 0.f, 0.f, 0.f);
            int r = bm + lrow;
            if (r < M) {
                if (k0 + lcol + 3 < K) {
                    v = *(const float4*)(A + (size_t)r * lda + k0 + lcol);
                } else {
                    float tmp[4];
                    #pragma unroll
                    for (int i = 0; i < 4; i++)
                        tmp[i] = (k0 + lcol + i < K) ? A[(size_t)r * lda + k0 + lcol + i] : 0.f;
                    v = make_float4(tmp[0], tmp[1], tmp[2], tmp[3]);
                }
            }
            As[lcol + 0][lrow] = v.x;
            As[lcol + 1][lrow] = v.y;
            As[lcol + 2][lrow] = v.z;
            As[lcol + 3][lrow] = v.w;
        }
        {
            float4 v = make_float4(0.f, 0.f, 0.f, 0.f);
            int r = bn + lrow;
            if (r < N) {
                if (k0 + lcol + 3 < K) {
                    v = *(const float4*)(B + (size_t)r * ldb + k0 + lcol);
                } else {
                    float tmp[4];
                    #pragma unroll
                    for (int i = 0; i < 4; i++)
                        tmp[i] = (k0 + lcol + i < K) ? B[(size_t)r * ldb + k0 + lcol + i] : 0.f;
                    v = make_float4(tmp[0], tmp[1], tmp[2], tmp[3]);
                }
            }
            Bs[lcol + 0][lrow] = v.x;
            Bs[lcol + 1][lrow] = v.y;
            Bs[lcol + 2][lrow] = v.z;
            Bs[lcol + 3][lrow] = v.w;
        }
        __syncthreads();

        #pragma unroll
        for (int k = 0; k < BK; k++) {
            float a[TM], b[TN];
            #pragma unroll
            for (int i = 0; i < TM; i++) a[i] = As[k][ty * TM + i];
            #pragma unroll
            for (int j = 0; j < TN; j++) b[j] = Bs[k][tx * TN + j];
            #pragma unroll
            for (int i = 0; i < TM; i++)
                #pragma unroll
                for (int j = 0; j < TN; j++)
                    acc[i][j] = fmaf(a[i], b[j], acc[i][j]);
        }
        __syncthreads();
    }

    #pragma unroll
    for (int i = 0; i < TM; i++) {
        int r = bm + ty * TM + i;
        if (r >= M) continue;
        #pragma unroll
        for (int j = 0; j < TN; j++) {
            int c = bn + tx * TN + j;
            if (c >= N) continue;
            float v = acc[i][j];
            if (beta != 0.f) v += beta * C[(size_t)r * ldc + c];
            if (bias) v += bias[c];
            if (act == 1) {
                v = (v > 20.f) ? v : log1pf(expf(v));
            }
            C[(size_t)r * ldc + c] = v;
        }
    }
}

// ---------------- x_proj split-K (M=1024, N=80, K=1536) ----------------
#define XP_KS 8
__global__ __launch_bounds__(256) void xproj_splitk_kernel(
    const float* __restrict__ A,    // [SEQ][DI]
    const float* __restrict__ Bw,   // [PROJW][DI]
    float* __restrict__ C)          // [SEQ][PROJW], pre-zeroed
{
    const int mb = blockIdx.x * 64;
    const int kb = blockIdx.y * (DI / XP_KS);   // 192-chunk
    __shared__ float As[16][64];
    __shared__ float Bs[16][80];
    const int tid = threadIdx.x;
    const int tx = tid & 15, ty = tid >> 4;
    float acc[4][5];
    #pragma unroll
    for (int i = 0; i < 4; i++)
        #pragma unroll
        for (int j = 0; j < 5; j++) acc[i][j] = 0.f;

    for (int k0 = 0; k0 < DI / XP_KS; k0 += 16) {
        // load A tile (transposed): As[k][m]
        {
            int m = tid >> 2;               // 0..63
            int kq = (tid & 3) * 4;         // 0,4,8,12
            float4 v = *(const float4*)(A + (size_t)(mb + m) * DI + kb + k0 + kq);
            As[kq + 0][m] = v.x;
            As[kq + 1][m] = v.y;
            As[kq + 2][m] = v.z;
            As[kq + 3][m] = v.w;
        }
        // load B tile: Bs[k][n]
        #pragma unroll
        for (int j = 0; j < 5; j++) {
            int idx = tid + 256 * j;        // < 1280
            int k = idx / 80;
            int n = idx - k * 80;
            Bs[k][n] = Bw[(size_t)n * DI + kb + k0 + k];
        }
        __syncthreads();
        #pragma unroll
        for (int k = 0; k < 16; k++) {
            float a[4], b[5];
            #pragma unroll
            for (int i = 0; i < 4; i++) a[i] = As[k][ty + 16 * i];
            #pragma unroll
            for (int j = 0; j < 5; j++) b[j] = Bs[k][tx + 16 * j];
            #pragma unroll
            for (int i = 0; i < 4; i++)
                #pragma unroll
                for (int j = 0; j < 5; j++)
                    acc[i][j] = fmaf(a[i], b[j], acc[i][j]);
        }
        __syncthreads();
    }
    #pragma unroll
    for (int i = 0; i < 4; i++)
        #pragma unroll
        for (int j = 0; j < 5; j++)
            atomicAdd(&C[(size_t)(mb + ty + 16 * i) * PROJW + tx + 16 * j], acc[i][j]);
}

// ---------------- causal depthwise conv (width 4) + silu ----------------
__global__ void conv_silu_kernel(const float* __restrict__ xz,
                                 const float* __restrict__ w,
                                 const float* __restrict__ b,
                                 float* __restrict__ out) {
    int c = blockIdx.x * 256 + threadIdx.x;
    int t = blockIdx.y;
    if (c >= DI) return;
    float acc = b[c];
    #pragma unroll
    for (int j = 0; j < 4; j++) {
        int tt = t - 3 + j;
        if (tt >= 0) acc = fmaf(xz[tt * (2 * DI) + c], w[c * 4 + j], acc);
    }
    float sg = 1.f / (1.f + __expf(-acc));
    out[t * DI + c] = acc * sg;
}

// ---------------- selective scan ----------------
__global__ void scan_kernel(float* __restrict__ u_y,
                            const float* __restrict__ dt,
                            const float* __restrict__ proj,
                            const float* __restrict__ A_log,
                            const float* __restrict__ Dsk)
{
    int d = blockIdx.x * 16 + (threadIdx.x >> 4);
    int n = threadIdx.x & 15;
    float An = -__expf(A_log[d * DST + n]);
    float Dv = Dsk[d];
    float z = 0.f;
    for (int t = 0; t < SEQ; t++) {
        float dtv = dt[t * DI + d];
        float u   = u_y[t * DI + d];
        float a   = __expf(dtv * An);
        float ea  = expf(a);            // precise: compounds over 1024 steps
        float bdu = dtv * u * proj[t * PROJW + DTR + n];
        z = fmaf(ea, z, bdu);
        float c = z * proj[t * PROJW + DTR + DST + n];
        c += __shfl_xor_sync(0xffffffffu, c, 8, 16);
        c += __shfl_xor_sync(0xffffffffu, c, 4, 16);
        c += __shfl_xor_sync(0xffffffffu, c, 2, 16);
        c += __shfl_xor_sync(0xffffffffu, c, 1, 16);
        if (n == 0) u_y[t * DI + d] = c + u * Dv;
    }
}

// ---------------- gate: gated = y * silu(res) ----------------
__global__ void gate_kernel(const float* __restrict__ y,
                            const float* __restrict__ xz,
                            float* __restrict__ out) {
    int idx = blockIdx.x * 256 + threadIdx.x;
    if (idx >= SEQ * DI) return;
    int t = idx / DI;
    int d = idx - t * DI;
    float r = xz[t * 2 * DI + DI + d];
    float sg = r / (1.f + __expf(-r));
    out[idx] = y[idx] * sg;
}

// ---------------- host launcher ----------------
extern "C" void kernel_launch(void* const* d_in, const int* in_sizes, int n_in,
                              void* d_out, int out_size) {
    const int*   tokens       = (const int*)d_in[0];
    const float* embedding    = (const float*)d_in[1];
    const float* norm_w       = (const float*)d_in[2];
    const float* in_proj_w    = (const float*)d_in[3];
    const float* conv_w       = (const float*)d_in[4];
    const float* conv_b       = (const float*)d_in[5];
    const float* x_proj_w     = (const float*)d_in[6];
    const float* dt_proj_w    = (const float*)d_in[7];
    const float* dt_proj_b    = (const float*)d_in[8];
    const float* A_log        = (const float*)d_in[9];
    const float* D_skip       = (const float*)d_in[10];
    const float* out_proj_w   = (const float*)d_in[11];
    const float* final_norm_w = (const float*)d_in[12];
    float* out = (float*)d_out;

    float *px, *ph, *pxz, *pxc, *pproj, *pdt, *pgated;
    __nv_bfloat16 *pwlog, *pwin, *pwout, *pa3;
    cudaGetSymbolAddress((void**)&px,     g_x);
    cudaGetSymbolAddress((void**)&ph,     g_h);
    cudaGetSymbolAddress((void**)&pxz,    g_xz);
    cudaGetSymbolAddress((void**)&pxc,    g_xc);
    cudaGetSymbolAddress((void**)&pproj,  g_proj);
    cudaGetSymbolAddress((void**)&pdt,    g_dt);
    cudaGetSymbolAddress((void**)&pgated, g_gated);
    cudaGetSymbolAddress((void**)&pwlog,  g_w_logits);
    cudaGetSymbolAddress((void**)&pwin,   g_w_in);
    cudaGetSymbolAddress((void**)&pwout,  g_w_out);
    cudaGetSymbolAddress((void**)&pa3,    g_a3);

    // ---- weight split-3 conversions (every launch; deterministic) ----
    {
        size_t n;
        n = (size_t)NVOCAB * DM;
        split3_B_kernel<<<(unsigned)((n + 255) / 256), 256>>>(embedding, pwlog, NVOCAB, DM);
        n = (size_t)NLAYER * 2 * DI * DM;
        split3_B_kernel<<<(unsigned)((n + 255) / 256), 256>>>(in_proj_w, pwin, NLAYER * 2 * DI, DM);
        n = (size_t)NLAYER * DM * DI;
        split3_B_kernel<<<(unsigned)((n + 255) / 256), 256>>>(out_proj_w, pwout, NLAYER * DM, DI);
    }

    gather_kernel<<<SEQ, 256>>>(tokens, embedding, px);

    for (int i = 0; i < NLAYER; i++) {
        // h = rmsnorm(x)
        rmsnorm_kernel<<<SEQ, 256>>>(px, norm_w + i * DM, ph);

        // xz = h @ in_proj^T  (tensor path)
        split3_A_kernel<<<(SEQ * DM + 255) / 256, 256>>>(ph, pa3, SEQ, DM);
        gemm_bf16_nt_kernel<<<dim3(2 * DI / 128, SEQ / 128), 256>>>(
            pa3, pwin + (size_t)i * 2 * DI * K3_DM,
            pxz, 2 * DI, 2 * DI, K3_DM, 0);

        // xi = silu(conv(xz[:, :DI]))
        conv_silu_kernel<<<dim3(DI / 256, SEQ), 256>>>(
            pxz, conv_w + (size_t)i * DI * 4, conv_b + i * DI, pxc);

        // proj = xi @ x_proj^T  (split-K, atomic)
        cudaMemsetAsync(pproj, 0, (size_t)SEQ * PROJW * sizeof(float), 0);
        xproj_splitk_kernel<<<dim3(SEQ / 64, XP_KS), 256>>>(
            pxc, x_proj_w + (size_t)i * PROJW * DI, pproj);

        // dt = softplus(proj[:, :48] @ dt_proj^T + b)
        gemm_nt_kernel<<<dim3(DI / BN, SEQ / BM), 256>>>(
            pproj, PROJW, dt_proj_w + (size_t)i * DI * DTR, DTR,
            pdt, DI, SEQ, DI, DTR, dt_proj_b + i * DI, 1, 0.f);

        // selective scan: pxc (u) -> pxc (y)
        scan_kernel<<<DI / 16, 256>>>(
            pxc, pdt, pproj, A_log + (size_t)i * DI * DST, D_skip + i * DI);

        // gated = y * silu(res)
        gate_kernel<<<(SEQ * DI + 255) / 256, 256>>>(pxc, pxz, pgated);

        // x += gated @ out_proj^T  (tensor path, addC)
        split3_A_kernel<<<(SEQ * DI + 255) / 256, 256>>>(pgated, pa3, SEQ, DI);
        gemm_bf16_nt_kernel<<<dim3(DM / 128, SEQ / 128), 256>>>(
            pa3, pwout + (size_t)i * DM * K3_DI,
            px, DM, DM, K3_DI, 1);
    }

    // final rmsnorm + logits (tensor path)
    rmsnorm_kernel<<<SEQ, 256>>>(px, final_norm_w, ph);
    split3_A_kernel<<<(SEQ * DM + 255) / 256, 256>>>(ph, pa3, SEQ, DM);
    gemm_bf16_nt_kernel<<<dim3(NVOCAB / 128, SEQ / 128), 256>>>(
        pa3, pwlog, out, NVOCAB, NVOCAB, K3_DM, 0);
}

// round 17
// speedup vs baseline: 2.0720x; 1.0589x over previous
#include <cuda_runtime.h>
#include <cuda_bf16.h>
#include <stdint.h>
#include <math.h>

#define SEQ 1024
#define DM 768
#define DI 1536
#define DTR 48
#define DST 16
#define NLAYER 4
#define NVOCAB 32000
#define PROJW 80   // DTR + 2*DST

#define K3_DM (3 * DM)    // 2304
#define K3_DI (3 * DI)    // 4608

// ---------------- scratch (device globals; no allocation allowed) ----------------
__device__ float g_x[SEQ * DM];
__device__ float g_h[SEQ * DM];
__device__ float g_xz[SEQ * 2 * DI];
__device__ float g_xc[SEQ * DI];
__device__ float g_proj[SEQ * PROJW];
__device__ float g_dt[SEQ * DI];
__device__ float g_gated[SEQ * DI];

__device__ __nv_bfloat16 g_w_logits[(size_t)NVOCAB * K3_DM];
__device__ __nv_bfloat16 g_w_in[(size_t)NLAYER * 2 * DI * K3_DM];
__device__ __nv_bfloat16 g_w_out[(size_t)NLAYER * DM * K3_DI];
__device__ __nv_bfloat16 g_a3[(size_t)SEQ * K3_DI];

// ---------------- fp32 -> (hi,lo) bf16 split ----------------
__device__ __forceinline__ void split_bf16(float v, __nv_bfloat16& hi, __nv_bfloat16& lo) {
    hi = __float2bfloat16_rn(v);
    lo = __float2bfloat16_rn(v - __bfloat162float(hi));
}

__global__ void split3_B_kernel(const float* __restrict__ W,
                                __nv_bfloat16* __restrict__ out,
                                int N, int K) {
    size_t idx = (size_t)blockIdx.x * 256 + threadIdx.x;
    if (idx >= (size_t)N * K) return;
    int n = (int)(idx / K);
    int k = (int)(idx - (size_t)n * K);
    __nv_bfloat16 hi, lo;
    split_bf16(W[idx], hi, lo);
    __nv_bfloat16* row = out + (size_t)n * 3 * K;
    row[k] = hi;
    row[K + k] = hi;
    row[2 * K + k] = lo;
}

__global__ void split3_A_kernel(const float* __restrict__ Xm,
                                __nv_bfloat16* __restrict__ out,
                                int M, int K) {
    size_t idx = (size_t)blockIdx.x * 256 + threadIdx.x;
    if (idx >= (size_t)M * K) return;
    int m = (int)(idx / K);
    int k = (int)(idx - (size_t)m * K);
    __nv_bfloat16 hi, lo;
    split_bf16(Xm[idx], hi, lo);
    __nv_bfloat16* row = out + (size_t)m * 3 * K;
    row[k] = hi;
    row[K + k] = lo;
    row[2 * K + k] = hi;
}

// ---------------- embedding gather ----------------
__global__ void gather_kernel(const int* __restrict__ tokens,
                              const float* __restrict__ emb,
                              float* __restrict__ x) {
    int t = blockIdx.x;
    int tok = tokens[t];
    const float* src = emb + (size_t)tok * DM;
    for (int c = threadIdx.x; c < DM; c += blockDim.x)
        x[t * DM + c] = src[c];
}

// ---------------- rmsnorm ----------------
__global__ void rmsnorm_kernel(const float* __restrict__ in,
                               const float* __restrict__ w,
                               float* __restrict__ out) {
    int t = blockIdx.x;
    const float* row = in + t * DM;
    __shared__ float red[8];
    float s = 0.f;
    for (int c = threadIdx.x; c < DM; c += 256) {
        float v = row[c];
        s += v * v;
    }
    #pragma unroll
    for (int o = 16; o; o >>= 1) s += __shfl_xor_sync(0xffffffffu, s, o);
    if ((threadIdx.x & 31) == 0) red[threadIdx.x >> 5] = s;
    __syncthreads();
    float tot = 0.f;
    #pragma unroll
    for (int i = 0; i < 8; i++) tot += red[i];
    float rs = rsqrtf(tot * (1.0f / DM) + 1e-5f);
    for (int c = threadIdx.x; c < DM; c += 256)
        out[t * DM + c] = row[c] * rs * w[c];
}

// ================= tensor-core bf16 NT GEMM (mma.sync + ldmatrix + cp.async) =================
// C[M,N] = A[M,K]*B[N,K]^T, fp32 accumulate. M,N multiples of 128, K of 32.
// Block 128x128, 8 warps (4 in M x 2 in N), warp tile 32x64, mma.m16n8k16.
// 2-stage cp.async double buffer; fragments via ldmatrix.x4.
#define SPAD 40  // smem row stride in bf16 elements (conflict-free, 16B-aligned rows)

__device__ __forceinline__ uint32_t smem_u32(const void* p) {
    uint32_t a;
    asm("{ .reg .u64 t; cvta.to.shared.u64 t, %1; cvt.u32.u64 %0, t; }" : "=r"(a) : "l"(p));
    return a;
}

__device__ __forceinline__ void cp16(uint32_t s, const void* g) {
    asm volatile("cp.async.cg.shared.global [%0], [%1], 16;" :: "r"(s), "l"(g));
}

__device__ __forceinline__ void ldsm4(uint32_t& r0, uint32_t& r1, uint32_t& r2, uint32_t& r3,
                                      uint32_t addr) {
    asm volatile("ldmatrix.sync.aligned.m8n8.x4.shared.b16 {%0,%1,%2,%3}, [%4];"
                 : "=r"(r0), "=r"(r1), "=r"(r2), "=r"(r3) : "r"(addr));
}

__device__ __forceinline__ void mma_bf16(float* c, const uint32_t* a, const uint32_t* b) {
    asm volatile(
        "mma.sync.aligned.m16n8k16.row.col.f32.bf16.bf16.f32 "
        "{%0,%1,%2,%3}, {%4,%5,%6,%7}, {%8,%9}, {%0,%1,%2,%3};\n"
        : "+f"(c[0]), "+f"(c[1]), "+f"(c[2]), "+f"(c[3])
        : "r"(a[0]), "r"(a[1]), "r"(a[2]), "r"(a[3]), "r"(b[0]), "r"(b[1]));
}

__global__ __launch_bounds__(256) void gemm_bf16_nt_kernel(
    const __nv_bfloat16* __restrict__ A,
    const __nv_bfloat16* __restrict__ B,
    float* __restrict__ C, int ldc,
    int N, int K, int addC)
{
    __shared__ __nv_bfloat16 As[2][128 * SPAD];
    __shared__ __nv_bfloat16 Bs[2][128 * SPAD];

    const int tid  = threadIdx.x;
    const int lane = tid & 31;
    const int warp = tid >> 5;
    const int g = lane >> 2;      // group id (0..7)
    const int t = lane & 3;       // thread in group (0..3)
    const int wm = (warp >> 1) * 32;
    const int wn = (warp & 1) * 64;
    const int bm = blockIdx.y * 128;
    const int bn = blockIdx.x * 128;

    const __nv_bfloat16* Abase = A + (size_t)bm * K;
    const __nv_bfloat16* Bbase = B + (size_t)bn * K;

    // per-thread gmem tile loads: 2x 16B for A, 2x for B
    const int r0 = tid >> 2;            // 0..63
    const int c0 = (tid & 3) * 8;       // 0,8,16,24 (bf16 elems)

    const uint32_t sA0 = smem_u32(&As[0][0]);
    const uint32_t sB0 = smem_u32(&Bs[0][0]);
    const uint32_t stageBytes = 128 * SPAD * 2;

    // ldmatrix lane-dependent geometry (see derivation in analysis):
    // A x4 tiles: (row+0,k0),(row+8,k0),(row+0,k8),(row+8,k8) -> {a0,a1,a2,a3}
    const int lr   = lane & 7;
    const int aRow = ((lane >> 3) & 1) * 8 + lr;   // +0/+8 rows by tile pair
    const int aK   = (lane >> 4) * 8;              // k half by tile pair
    // B x4 tiles: (n+0,k0),(n+0,k8),(n+8,k0),(n+8,k8) -> {b[nf][0],b[nf][1],b[nf+1][0],b[nf+1][1]}
    const int bRow = (lane >> 4) * 8 + lr;         // +0/+8 n rows
    const int bK   = ((lane >> 3) & 1) * 8;        // k half

    float acc[2][8][4];
    #pragma unroll
    for (int f = 0; f < 2; f++)
        #pragma unroll
        for (int nf = 0; nf < 8; nf++)
            #pragma unroll
            for (int i = 0; i < 4; i++) acc[f][nf][i] = 0.f;

    const int niter = K / 32;

    // prologue: stage 0 via cp.async
    {
        const __nv_bfloat16* Ap = Abase + (size_t)r0 * K + c0;
        const __nv_bfloat16* Bp = Bbase + (size_t)r0 * K + c0;
        cp16(sA0 + (uint32_t)(r0 * SPAD + c0) * 2, Ap);
        cp16(sA0 + (uint32_t)((r0 + 64) * SPAD + c0) * 2, Ap + (size_t)64 * K);
        cp16(sB0 + (uint32_t)(r0 * SPAD + c0) * 2, Bp);
        cp16(sB0 + (uint32_t)((r0 + 64) * SPAD + c0) * 2, Bp + (size_t)64 * K);
        asm volatile("cp.async.commit_group;" ::: "memory");
    }

    for (int kt = 0; kt < niter; kt++) {
        asm volatile("cp.async.wait_group 0;" ::: "memory");
        __syncthreads();
        const int st = kt & 1;

        // prefetch next stage (overlaps with compute below)
        if (kt + 1 < niter) {
            const int ns = (kt + 1) & 1;
            const int kn = (kt + 1) * 32;
            const __nv_bfloat16* Ap = Abase + (size_t)r0 * K + kn + c0;
            const __nv_bfloat16* Bp = Bbase + (size_t)r0 * K + kn + c0;
            const uint32_t dA = sA0 + (uint32_t)ns * stageBytes;
            const uint32_t dB = sB0 + (uint32_t)ns * stageBytes;
            cp16(dA + (uint32_t)(r0 * SPAD + c0) * 2, Ap);
            cp16(dA + (uint32_t)((r0 + 64) * SPAD + c0) * 2, Ap + (size_t)64 * K);
            cp16(dB + (uint32_t)(r0 * SPAD + c0) * 2, Bp);
            cp16(dB + (uint32_t)((r0 + 64) * SPAD + c0) * 2, Bp + (size_t)64 * K);
            asm volatile("cp.async.commit_group;" ::: "memory");
        }

        const uint32_t aBase = sA0 + (uint32_t)st * stageBytes;
        const uint32_t bBase = sB0 + (uint32_t)st * stageBytes;
        #pragma unroll
        for (int ks = 0; ks < 2; ks++) {
            const int kk0 = ks * 16;
            uint32_t a[2][4];
            #pragma unroll
            for (int f = 0; f < 2; f++) {
                uint32_t addr = aBase +
                    (uint32_t)(((wm + f * 16 + aRow) * SPAD) + aK + kk0) * 2;
                ldsm4(a[f][0], a[f][1], a[f][2], a[f][3], addr);
            }
            uint32_t b[8][2];
            #pragma unroll
            for (int nf2 = 0; nf2 < 4; nf2++) {
                uint32_t addr = bBase +
                    (uint32_t)(((wn + nf2 * 16 + bRow) * SPAD) + bK + kk0) * 2;
                ldsm4(b[nf2 * 2][0], b[nf2 * 2][1], b[nf2 * 2 + 1][0], b[nf2 * 2 + 1][1], addr);
            }
            #pragma unroll
            for (int f = 0; f < 2; f++)
                #pragma unroll
                for (int nf = 0; nf < 8; nf++)
                    mma_bf16(acc[f][nf], a[f], b[nf]);
        }
    }

    // epilogue (same mapping as validated R6 kernel)
    #pragma unroll
    for (int f = 0; f < 2; f++) {
        int row = bm + wm + f * 16 + g;
        #pragma unroll
        for (int nf = 0; nf < 8; nf++) {
            int col = bn + wn + nf * 8 + t * 2;
            float* p0 = C + (size_t)row * ldc + col;
            float* p1 = C + (size_t)(row + 8) * ldc + col;
            if (addC) {
                p0[0] += acc[f][nf][0];
                p0[1] += acc[f][nf][1];
                p1[0] += acc[f][nf][2];
                p1[1] += acc[f][nf][3];
            } else {
                p0[0] = acc[f][nf][0];
                p0[1] = acc[f][nf][1];
                p1[0] = acc[f][nf][2];
                p1[1] = acc[f][nf][3];
            }
        }
    }
}

// ---------------- SIMT fp32 NT gemm (kept for dt_proj) ----------------
#define BM 128
#define BN 128
#define BK 8
#define TM 8
#define TN 8

__global__ __launch_bounds__(256) void gemm_nt_kernel(
    const float* __restrict__ A, int lda,
    const float* __restrict__ B, int ldb,
    float* __restrict__ C, int ldc,
    int M, int N, int K,
    const float* __restrict__ bias, int act, float beta)
{
    __shared__ float As[BK][BM];
    __shared__ float Bs[BK][BN];

    int bm = blockIdx.y * BM;
    int bn = blockIdx.x * BN;
    int tid = threadIdx.x;
    int tx = tid & 15;
    int ty = tid >> 4;

    int lrow = tid >> 1;
    int lcol = (tid & 1) * 4;

    float acc[TM][TN];
    #pragma unroll
    for (int i = 0; i < TM; i++)
        #pragma unroll
        for (int j = 0; j < TN; j++) acc[i][j] = 0.f;

    for (int k0 = 0; k0 < K; k0 += BK) {
        {
            float4 v = make_float4(0.f, 0.f, 0.f, 0.f);
            int r = bm + lrow;
            if (r < M) {
                if (k0 + lcol + 3 < K) {
                    v = *(const float4*)(A + (size_t)r * lda + k0 + lcol);
                } else {
                    float tmp[4];
                    #pragma unroll
                    for (int i = 0; i < 4; i++)
                        tmp[i] = (k0 + lcol + i < K) ? A[(size_t)r * lda + k0 + lcol + i] : 0.f;
                    v = make_float4(tmp[0], tmp[1], tmp[2], tmp[3]);
                }
            }
            As[lcol + 0][lrow] = v.x;
            As[lcol + 1][lrow] = v.y;
            As[lcol + 2][lrow] = v.z;
            As[lcol + 3][lrow] = v.w;
        }
        {
            float4 v = make_float4(0.f, 0.f, 0.f, 0.f);
            int r = bn + lrow;
            if (r < N) {
                if (k0 + lcol + 3 < K) {
                    v = *(const float4*)(B + (size_t)r * ldb + k0 + lcol);
                } else {
                    float tmp[4];
                    #pragma unroll
                    for (int i = 0; i < 4; i++)
                        tmp[i] = (k0 + lcol + i < K) ? B[(size_t)r * ldb + k0 + lcol + i] : 0.f;
                    v = make_float4(tmp[0], tmp[1], tmp[2], tmp[3]);
                }
            }
            Bs[lcol + 0][lrow] = v.x;
            Bs[lcol + 1][lrow] = v.y;
            Bs[lcol + 2][lrow] = v.z;
            Bs[lcol + 3][lrow] = v.w;
        }
        __syncthreads();

        #pragma unroll
        for (int k = 0; k < BK; k++) {
            float a[TM], b[TN];
            #pragma unroll
            for (int i = 0; i < TM; i++) a[i] = As[k][ty * TM + i];
            #pragma unroll
            for (int j = 0; j < TN; j++) b[j] = Bs[k][tx * TN + j];
            #pragma unroll
            for (int i = 0; i < TM; i++)
                #pragma unroll
                for (int j = 0; j < TN; j++)
                    acc[i][j] = fmaf(a[i], b[j], acc[i][j]);
        }
        __syncthreads();
    }

    #pragma unroll
    for (int i = 0; i < TM; i++) {
        int r = bm + ty * TM + i;
        if (r >= M) continue;
        #pragma unroll
        for (int j = 0; j < TN; j++) {
            int c = bn + tx * TN + j;
            if (c >= N) continue;
            float v = acc[i][j];
            if (beta != 0.f) v += beta * C[(size_t)r * ldc + c];
            if (bias) v += bias[c];
            if (act == 1) {
                v = (v > 20.f) ? v : log1pf(expf(v));
            }
            C[(size_t)r * ldc + c] = v;
        }
    }
}

// ---------------- x_proj split-K (M=1024, N=80, K=1536) ----------------
#define XP_KS 8
__global__ __launch_bounds__(256) void xproj_splitk_kernel(
    const float* __restrict__ A,
    const float* __restrict__ Bw,
    float* __restrict__ C)
{
    const int mb = blockIdx.x * 64;
    const int kb = blockIdx.y * (DI / XP_KS);
    __shared__ float As[16][64];
    __shared__ float Bs[16][80];
    const int tid = threadIdx.x;
    const int tx = tid & 15, ty = tid >> 4;
    float acc[4][5];
    #pragma unroll
    for (int i = 0; i < 4; i++)
        #pragma unroll
        for (int j = 0; j < 5; j++) acc[i][j] = 0.f;

    for (int k0 = 0; k0 < DI / XP_KS; k0 += 16) {
        {
            int m = tid >> 2;
            int kq = (tid & 3) * 4;
            float4 v = *(const float4*)(A + (size_t)(mb + m) * DI + kb + k0 + kq);
            As[kq + 0][m] = v.x;
            As[kq + 1][m] = v.y;
            As[kq + 2][m] = v.z;
            As[kq + 3][m] = v.w;
        }
        #pragma unroll
        for (int j = 0; j < 5; j++) {
            int idx = tid + 256 * j;
            int k = idx / 80;
            int n = idx - k * 80;
            Bs[k][n] = Bw[(size_t)n * DI + kb + k0 + k];
        }
        __syncthreads();
        #pragma unroll
        for (int k = 0; k < 16; k++) {
            float a[4], b[5];
            #pragma unroll
            for (int i = 0; i < 4; i++) a[i] = As[k][ty + 16 * i];
            #pragma unroll
            for (int j = 0; j < 5; j++) b[j] = Bs[k][tx + 16 * j];
            #pragma unroll
            for (int i = 0; i < 4; i++)
                #pragma unroll
                for (int j = 0; j < 5; j++)
                    acc[i][j] = fmaf(a[i], b[j], acc[i][j]);
        }
        __syncthreads();
    }
    #pragma unroll
    for (int i = 0; i < 4; i++)
        #pragma unroll
        for (int j = 0; j < 5; j++)
            atomicAdd(&C[(size_t)(mb + ty + 16 * i) * PROJW + tx + 16 * j], acc[i][j]);
}

// ---------------- causal depthwise conv (width 4) + silu ----------------
__global__ void conv_silu_kernel(const float* __restrict__ xz,
                                 const float* __restrict__ w,
                                 const float* __restrict__ b,
                                 float* __restrict__ out) {
    int c = blockIdx.x * 256 + threadIdx.x;
    int t = blockIdx.y;
    if (c >= DI) return;
    float acc = b[c];
    #pragma unroll
    for (int j = 0; j < 4; j++) {
        int tt = t - 3 + j;
        if (tt >= 0) acc = fmaf(xz[tt * (2 * DI) + c], w[c * 4 + j], acc);
    }
    float sg = 1.f / (1.f + __expf(-acc));
    out[t * DI + c] = acc * sg;
}

// ---------------- selective scan ----------------
__global__ void scan_kernel(float* __restrict__ u_y,
                            const float* __restrict__ dt,
                            const float* __restrict__ proj,
                            const float* __restrict__ A_log,
                            const float* __restrict__ Dsk)
{
    int d = blockIdx.x * 16 + (threadIdx.x >> 4);
    int n = threadIdx.x & 15;
    float An = -__expf(A_log[d * DST + n]);
    float Dv = Dsk[d];
    float z = 0.f;
    for (int t = 0; t < SEQ; t++) {
        float dtv = dt[t * DI + d];
        float u   = u_y[t * DI + d];
        float a   = __expf(dtv * An);
        float ea  = expf(a);            // precise: compounds over 1024 steps
        float bdu = dtv * u * proj[t * PROJW + DTR + n];
        z = fmaf(ea, z, bdu);
        float c = z * proj[t * PROJW + DTR + DST + n];
        c += __shfl_xor_sync(0xffffffffu, c, 8, 16);
        c += __shfl_xor_sync(0xffffffffu, c, 4, 16);
        c += __shfl_xor_sync(0xffffffffu, c, 2, 16);
        c += __shfl_xor_sync(0xffffffffu, c, 1, 16);
        if (n == 0) u_y[t * DI + d] = c + u * Dv;
    }
}

// ---------------- gate: gated = y * silu(res) ----------------
__global__ void gate_kernel(const float* __restrict__ y,
                            const float* __restrict__ xz,
                            float* __restrict__ out) {
    int idx = blockIdx.x * 256 + threadIdx.x;
    if (idx >= SEQ * DI) return;
    int t = idx / DI;
    int d = idx - t * DI;
    float r = xz[t * 2 * DI + DI + d];
    float sg = r / (1.f + __expf(-r));
    out[idx] = y[idx] * sg;
}

// ---------------- host launcher ----------------
extern "C" void kernel_launch(void* const* d_in, const int* in_sizes, int n_in,
                              void* d_out, int out_size) {
    const int*   tokens       = (const int*)d_in[0];
    const float* embedding    = (const float*)d_in[1];
    const float* norm_w       = (const float*)d_in[2];
    const float* in_proj_w    = (const float*)d_in[3];
    const float* conv_w       = (const float*)d_in[4];
    const float* conv_b       = (const float*)d_in[5];
    const float* x_proj_w     = (const float*)d_in[6];
    const float* dt_proj_w    = (const float*)d_in[7];
    const float* dt_proj_b    = (const float*)d_in[8];
    const float* A_log        = (const float*)d_in[9];
    const float* D_skip       = (const float*)d_in[10];
    const float* out_proj_w   = (const float*)d_in[11];
    const float* final_norm_w = (const float*)d_in[12];
    float* out = (float*)d_out;

    float *px, *ph, *pxz, *pxc, *pproj, *pdt, *pgated;
    __nv_bfloat16 *pwlog, *pwin, *pwout, *pa3;
    cudaGetSymbolAddress((void**)&px,     g_x);
    cudaGetSymbolAddress((void**)&ph,     g_h);
    cudaGetSymbolAddress((void**)&pxz,    g_xz);
    cudaGetSymbolAddress((void**)&pxc,    g_xc);
    cudaGetSymbolAddress((void**)&pproj,  g_proj);
    cudaGetSymbolAddress((void**)&pdt,    g_dt);
    cudaGetSymbolAddress((void**)&pgated, g_gated);
    cudaGetSymbolAddress((void**)&pwlog,  g_w_logits);
    cudaGetSymbolAddress((void**)&pwin,   g_w_in);
    cudaGetSymbolAddress((void**)&pwout,  g_w_out);
    cudaGetSymbolAddress((void**)&pa3,    g_a3);

    // ---- weight split-3 conversions (every launch; deterministic) ----
    {
        size_t n;
        n = (size_t)NVOCAB * DM;
        split3_B_kernel<<<(unsigned)((n + 255) / 256), 256>>>(embedding, pwlog, NVOCAB, DM);
        n = (size_t)NLAYER * 2 * DI * DM;
        split3_B_kernel<<<(unsigned)((n + 255) / 256), 256>>>(in_proj_w, pwin, NLAYER * 2 * DI, DM);
        n = (size_t)NLAYER * DM * DI;
        split3_B_kernel<<<(unsigned)((n + 255) / 256), 256>>>(out_proj_w, pwout, NLAYER * DM, DI);
    }

    gather_kernel<<<SEQ, 256>>>(tokens, embedding, px);

    for (int i = 0; i < NLAYER; i++) {
        // h = rmsnorm(x)
        rmsnorm_kernel<<<SEQ, 256>>>(px, norm_w + i * DM, ph);

        // xz = h @ in_proj^T  (tensor path)
        split3_A_kernel<<<(SEQ * DM + 255) / 256, 256>>>(ph, pa3, SEQ, DM);
        gemm_bf16_nt_kernel<<<dim3(2 * DI / 128, SEQ / 128), 256>>>(
            pa3, pwin + (size_t)i * 2 * DI * K3_DM,
            pxz, 2 * DI, 2 * DI, K3_DM, 0);

        // xi = silu(conv(xz[:, :DI]))
        conv_silu_kernel<<<dim3(DI / 256, SEQ), 256>>>(
            pxz, conv_w + (size_t)i * DI * 4, conv_b + i * DI, pxc);

        // proj = xi @ x_proj^T  (split-K, atomic)
        cudaMemsetAsync(pproj, 0, (size_t)SEQ * PROJW * sizeof(float), 0);
        xproj_splitk_kernel<<<dim3(SEQ / 64, XP_KS), 256>>>(
            pxc, x_proj_w + (size_t)i * PROJW * DI, pproj);

        // dt = softplus(proj[:, :48] @ dt_proj^T + b)
        gemm_nt_kernel<<<dim3(DI / BN, SEQ / BM), 256>>>(
            pproj, PROJW, dt_proj_w + (size_t)i * DI * DTR, DTR,
            pdt, DI, SEQ, DI, DTR, dt_proj_b + i * DI, 1, 0.f);

        // selective scan: pxc (u) -> pxc (y)
        scan_kernel<<<DI / 16, 256>>>(
            pxc, pdt, pproj, A_log + (size_t)i * DI * DST, D_skip + i * DI);

        // gated = y * silu(res)
        gate_kernel<<<(SEQ * DI + 255) / 256, 256>>>(pxc, pxz, pgated);

        // x += gated @ out_proj^T  (tensor path, addC)
        split3_A_kernel<<<(SEQ * DI + 255) / 256, 256>>>(pgated, pa3, SEQ, DI);
        gemm_bf16_nt_kernel<<<dim3(DM / 128, SEQ / 128), 256>>>(
            pa3, pwout + (size_t)i * DM * K3_DI,
            px, DM, DM, K3_DI, 1);
    }

    // final rmsnorm + logits (tensor path)
    rmsnorm_kernel<<<SEQ, 256>>>(px, final_norm_w, ph);
    split3_A_kernel<<<(SEQ * DM + 255) / 256, 256>>>(ph, pa3, SEQ, DM);
    gemm_bf16_nt_kernel<<<dim3(NVOCAB / 128, SEQ / 128), 256>>>(
        pa3, pwlog, out, NVOCAB, NVOCAB, K3_DM, 0);
}